// round 15
// baseline (speedup 1.0000x reference)
#include <cuda_runtime.h>
#include <cuda_bf16.h>
#include <cstdint>

#define SEQ   1024
#define BATCH 4
#define DM    1024
#define NH    16
#define HD    64
#define DFF   4096
#define NL    4
#define WIN   64
#define MTOT  (SEQ*BATCH)

// ======================= PTX helpers (sm_80+ features only) =======================
__device__ __forceinline__ uint32_t smem_to_u32(const void* p) {
    uint32_t a;
    asm("{ .reg .u64 t; cvta.to.shared.u64 t, %1; cvt.u32.u64 %0, t; }" : "=r"(a) : "l"(p));
    return a;
}
__device__ __forceinline__ void cpa16(uint32_t smem, const void* gmem) {
    asm volatile("cp.async.cg.shared.global [%0], [%1], 16;" :: "r"(smem), "l"(gmem) : "memory");
}
__device__ __forceinline__ void ldsm_x4(uint32_t* r, uint32_t addr) {
    asm volatile("ldmatrix.sync.aligned.m8n8.x4.shared.b16 {%0,%1,%2,%3}, [%4];"
        : "=r"(r[0]), "=r"(r[1]), "=r"(r[2]), "=r"(r[3]) : "r"(addr));
}
__device__ __forceinline__ void ldsm_x2(uint32_t* r, uint32_t addr) {
    asm volatile("ldmatrix.sync.aligned.m8n8.x2.shared.b16 {%0,%1}, [%2];"
        : "=r"(r[0]), "=r"(r[1]) : "r"(addr));
}
__device__ __forceinline__ void ldsm_x2t(uint32_t* r, uint32_t addr) {
    asm volatile("ldmatrix.sync.aligned.m8n8.x2.trans.shared.b16 {%0,%1}, [%2];"
        : "=r"(r[0]), "=r"(r[1]) : "r"(addr));
}
__device__ __forceinline__ void mma16816(float* c, const uint32_t* a, const uint32_t* b) {
    asm volatile(
        "mma.sync.aligned.m16n8k16.row.col.f32.bf16.bf16.f32 "
        "{%0,%1,%2,%3}, {%4,%5,%6,%7}, {%8,%9}, {%0,%1,%2,%3};"
        : "+f"(c[0]), "+f"(c[1]), "+f"(c[2]), "+f"(c[3])
        : "r"(a[0]), "r"(a[1]), "r"(a[2]), "r"(a[3]), "r"(b[0]), "r"(b[1]));
}

// ======================= scratch (device globals) =======================
__device__ __align__(256) float          g_xb   [MTOT * DM];
__device__ __align__(256) __nv_bfloat16  g_xh   [MTOT * DM];
__device__ __align__(256) __nv_bfloat16  g_xl   [MTOT * DM];
__device__ __align__(256) __nv_bfloat16  g_qkvh [MTOT * 3 * DM];
__device__ __align__(256) __nv_bfloat16  g_qkvl [MTOT * 3 * DM];
__device__ __align__(256) __nv_bfloat16  g_ah   [MTOT * DM];
__device__ __align__(256) __nv_bfloat16  g_al   [MTOT * DM];
__device__ __align__(256) float          g_delta[MTOT * DM];
__device__ __align__(256) __nv_bfloat16  g_fh   [MTOT * DFF];
__device__ __align__(256) __nv_bfloat16  g_fl   [MTOT * DFF];
__device__ __align__(256) __nv_bfloat16  g_wqh  [NL * 3 * DM * DM];
__device__ __align__(256) __nv_bfloat16  g_wql  [NL * 3 * DM * DM];
__device__ __align__(256) __nv_bfloat16  g_woh  [NL * DM * DM];
__device__ __align__(256) __nv_bfloat16  g_wol  [NL * DM * DM];
__device__ __align__(256) __nv_bfloat16  g_w1h  [NL * DFF * DM];
__device__ __align__(256) __nv_bfloat16  g_w1l  [NL * DFF * DM];
__device__ __align__(256) __nv_bfloat16  g_w2h  [NL * DM * DFF];
__device__ __align__(256) __nv_bfloat16  g_w2l  [NL * DM * DFF];

__device__ __forceinline__ void split1(float v, __nv_bfloat16& h, __nv_bfloat16& l) {
    h = __float2bfloat16(v);
    l = __float2bfloat16(v - __bfloat162float(h));
}
__device__ __forceinline__ void split4(const float* v, __nv_bfloat16* hp, __nv_bfloat16* lp) {
    __nv_bfloat16 h0, h1, h2, h3, l0, l1, l2, l3;
    split1(v[0], h0, l0); split1(v[1], h1, l1); split1(v[2], h2, l2); split1(v[3], h3, l3);
    __nv_bfloat162 hh0; hh0.x = h0; hh0.y = h1;
    __nv_bfloat162 hh1; hh1.x = h2; hh1.y = h3;
    __nv_bfloat162 ll0; ll0.x = l0; ll0.y = l1;
    __nv_bfloat162 ll1; ll1.x = l2; ll1.y = l3;
    *(__nv_bfloat162*)(hp)     = hh0;
    *(__nv_bfloat162*)(hp + 2) = hh1;
    *(__nv_bfloat162*)(lp)     = ll0;
    *(__nv_bfloat162*)(lp + 2) = ll1;
}
__device__ __forceinline__ void psplit2(float p0, float p1, uint32_t& hi, uint32_t& lo) {
    __nv_bfloat16 h0 = __float2bfloat16(p0), h1 = __float2bfloat16(p1);
    __nv_bfloat16 r0 = __float2bfloat16(p0 - __bfloat162float(h0));
    __nv_bfloat16 r1 = __float2bfloat16(p1 - __bfloat162float(h1));
    __nv_bfloat162 H; H.x = h0; H.y = h1;
    __nv_bfloat162 L; L.x = r0; L.y = r1;
    hi = *(uint32_t*)&H; lo = *(uint32_t*)&L;
}

// ======================= fused weight split =======================
__global__ void k_split_all(const float* __restrict__ Wqkv, const float* __restrict__ Wo,
                            const float* __restrict__ W1,   const float* __restrict__ W2,
                            __nv_bfloat16* wqh, __nv_bfloat16* wql,
                            __nv_bfloat16* woh, __nv_bfloat16* wol,
                            __nv_bfloat16* w1h, __nv_bfloat16* w1l,
                            __nv_bfloat16* w2h, __nv_bfloat16* w2l)
{
    const int N0 = NL * 3 * DM * DM / 4;
    const int N1 = NL * DM * DM / 4;
    const int N2 = NL * DFF * DM / 4;
    const int N3 = NL * DM * DFF / 4;
    int i = blockIdx.x * blockDim.x + threadIdx.x;
    const float* s; __nv_bfloat16 *h, *l; int j;
    if (i < N0)                { s = Wqkv; h = wqh; l = wql; j = i; }
    else if (i < N0+N1)        { s = Wo;   h = woh; l = wol; j = i - N0; }
    else if (i < N0+N1+N2)     { s = W1;   h = w1h; l = w1l; j = i - N0 - N1; }
    else if (i < N0+N1+N2+N3)  { s = W2;   h = w2h; l = w2l; j = i - N0 - N1 - N2; }
    else return;
    float v[4];
    *(float4*)v = *(const float4*)(s + (size_t)j * 4);
    split4(v, h + (size_t)j * 4, l + (size_t)j * 4);
}

// ======================= layout transposes =======================
__global__ void k_in(const float* __restrict__ x, float* __restrict__ xb,
                     __nv_bfloat16* __restrict__ xh, __nv_bfloat16* __restrict__ xl) {
    int idx = blockIdx.x * blockDim.x + threadIdx.x;
    if (idx >= MTOT * DM) return;
    int kcol = idx % DM;
    int row  = idx / DM;
    int b = row / SEQ, s = row % SEQ;
    float v = x[((size_t)(s * BATCH + b)) * DM + kcol];
    xb[idx] = v;
    __nv_bfloat16 h, l; split1(v, h, l);
    xh[idx] = h; xl[idx] = l;
}

__global__ void k_out(const float* __restrict__ xb, float* __restrict__ out) {
    int idx = blockIdx.x * blockDim.x + threadIdx.x;
    if (idx >= MTOT * DM) return;
    int kcol = idx % DM;
    int r    = idx / DM;
    int b = r % BATCH, s = r / BATCH;
    out[idx] = xb[((size_t)(b * SEQ + s)) * DM + kcol];
}

// ======================= HMMA GEMM: 256x128 tile, 512 threads (16 warps) =======================
// Same tile/pipeline as the 4177us baseline; 4x4 warp grid (64x32 per warp)
// doubles warps/SMSP from 2 to 4 to hide mma/ldsm latency.
#define PAD    72
#define AT_B   (256 * PAD * 2)        // 36864
#define BT_B   (128 * PAD * 2)        // 18432
#define STG_B  (2 * AT_B + 2 * BT_B)  // 110592
#define TG_SMEM (2 * STG_B)           // 221184

template<int RELU, int SPLIT>
__global__ void __launch_bounds__(512, 1)
k_tgemm(const __nv_bfloat16* __restrict__ Ah, const __nv_bfloat16* __restrict__ Al,
        const __nv_bfloat16* __restrict__ Bh, const __nv_bfloat16* __restrict__ Bl,
        const float* __restrict__ bias,
        float* __restrict__ Cf, __nv_bfloat16* __restrict__ Ch, __nv_bfloat16* __restrict__ Cl,
        int M, int N, int K)
{
    extern __shared__ char dsm[];
    const uint32_t sbase = smem_to_u32(dsm);
    const int tid  = threadIdx.x;
    const int lane = tid & 31;
    const int wid  = tid >> 5;
    const int wm   = wid >> 2;          // 0..3 (64-row slab)
    const int wn   = wid & 3;           // 0..3 (32-col slab)
    const int m0 = blockIdx.y * 256;
    const int n0 = blockIdx.x * 128;
    const int nch = K >> 6;

    float acc[4][4][4];
#pragma unroll
    for (int mt = 0; mt < 4; mt++)
#pragma unroll
        for (int nt = 0; nt < 4; nt++)
#pragma unroll
            for (int i = 0; i < 4; i++) acc[mt][nt][i] = 0.f;

    const uint32_t aoff = ((wm * 64 + (lane & 15)) * PAD + (lane >> 4) * 8) * 2;
    const uint32_t boff = ((wn * 32 + (lane & 7)) * PAD + ((lane >> 3) & 1) * 8) * 2;

    // tile loader: 6144 x 16B pieces per chunk, 12 per thread (512 threads)
    auto load_chunk = [&](int cc, int s) {
        uint32_t stg = sbase + s * STG_B;
#pragma unroll
        for (int i = 0; i < 12; i++) {
            int idx = tid + i * 512;
            if (idx < 4096) {
                int t = idx >> 11, loc = idx & 2047;
                int r = loc >> 3, c = loc & 7;
                cpa16(stg + t * AT_B + r * (PAD * 2) + c * 16,
                      (t ? Al : Ah) + (size_t)(m0 + r) * K + cc * 64 + c * 8);
            } else {
                int j = idx - 4096;
                int t = j >> 10, loc = j & 1023;
                int r = loc >> 3, c = loc & 7;
                cpa16(stg + 2 * AT_B + t * BT_B + r * (PAD * 2) + c * 16,
                      (t ? Bl : Bh) + (size_t)(n0 + r) * K + cc * 64 + c * 8);
            }
        }
    };

    load_chunk(0, 0);
    asm volatile("cp.async.commit_group;" ::: "memory");

    for (int cch = 0; cch < nch; cch++) {
        __syncthreads();
        if (cch + 1 < nch) load_chunk(cch + 1, (cch + 1) & 1);
        asm volatile("cp.async.commit_group;" ::: "memory");
        asm volatile("cp.async.wait_group 1;" ::: "memory");
        __syncthreads();

        const uint32_t stg = sbase + (cch & 1) * STG_B;
        const uint32_t Ah_s = stg, Al_s = stg + AT_B;
        const uint32_t Bh_s = stg + 2 * AT_B, Bl_s = stg + 2 * AT_B + BT_B;

#pragma unroll
        for (int ks = 0; ks < 4; ks++) {
            uint32_t bh[4][2], bl[4][2];
#pragma unroll
            for (int nt = 0; nt < 4; nt++) {
                uint32_t off = boff + (nt * 8 * PAD + ks * 16) * 2;
                ldsm_x2(bh[nt], Bh_s + off);
                ldsm_x2(bl[nt], Bl_s + off);
            }
#pragma unroll
            for (int mt = 0; mt < 4; mt++) {
                uint32_t ah[4], al[4];
                uint32_t off = aoff + (mt * 16 * PAD + ks * 16) * 2;
                ldsm_x4(ah, Ah_s + off);
                ldsm_x4(al, Al_s + off);
#pragma unroll
                for (int nt = 0; nt < 4; nt++) {
                    mma16816(acc[mt][nt], ah, bh[nt]);
                    mma16816(acc[mt][nt], ah, bl[nt]);
                    mma16816(acc[mt][nt], al, bh[nt]);
                }
            }
        }
    }

    const int r0 = m0 + wm * 64 + (lane >> 2);
    const int c0 = n0 + wn * 32 + 2 * (lane & 3);
#pragma unroll
    for (int mt = 0; mt < 4; mt++) {
#pragma unroll
        for (int nt = 0; nt < 4; nt++) {
            int col = c0 + nt * 8;
            float b0 = bias[col], b1 = bias[col + 1];
#pragma unroll
            for (int half = 0; half < 2; half++) {
                int row = r0 + mt * 16 + half * 8;
                float v0 = acc[mt][nt][2 * half + 0] + b0;
                float v1 = acc[mt][nt][2 * half + 1] + b1;
                if (RELU) { v0 = fmaxf(v0, 0.f); v1 = fmaxf(v1, 0.f); }
                size_t off = (size_t)row * N + col;
                if (!SPLIT) {
                    float2 w = {v0, v1};
                    *(float2*)(Cf + off) = w;
                } else {
                    uint32_t hi, lo;
                    psplit2(v0, v1, hi, lo);
                    *(uint32_t*)(Ch + off) = hi;
                    *(uint32_t*)(Cl + off) = lo;
                }
            }
        }
    }
}

// ======================= HMMA banded flash attention (no running max) =======================
#define AP     72
#define AROWB  (AP * 2)
#define QTILEB (128 * AROWB)
#define ATILEB (64 * AROWB)
#define ASTGB  (4 * ATILEB)
#define ATT_SMEM (2 * QTILEB + 2 * ASTGB)

__global__ void __launch_bounds__(256, 1)
k_attn(const __nv_bfloat16* __restrict__ qh, const __nv_bfloat16* __restrict__ ql,
       __nv_bfloat16* __restrict__ ah, __nv_bfloat16* __restrict__ al)
{
    extern __shared__ char asm_[];
    const uint32_t sbase = smem_to_u32(asm_);
    const uint32_t Qh_s = sbase, Ql_s = sbase + QTILEB;
    const uint32_t stg0 = sbase + 2 * QTILEB;

    const int tid = threadIdx.x;
    const int lane = tid & 31;
    const int w = tid >> 5;
    const int Qb = (gridDim.x - 1) - blockIdx.x;     // heavy tiles first
    const int h = blockIdx.y, b = blockIdx.z;
    const int nch = min(16, 2 * Qb + 3);
    const size_t rstr = 3 * DM;
    const size_t rowoff0 = (size_t)(b * SEQ) * rstr + h * HD;

#pragma unroll
    for (int i = 0; i < 8; i++) {
        int lin = i * 256 + tid;
        int hl = lin >> 10, loc = lin & 1023;
        int r = loc >> 3, p = loc & 7;
        const __nv_bfloat16* src = (hl ? ql : qh) + rowoff0 + (size_t)(Qb * 128 + r) * rstr + p * 8;
        cpa16((hl ? Ql_s : Qh_s) + r * AROWB + p * 16, src);
    }
#pragma unroll
    for (int i = 0; i < 8; i++) {
        int lin = i * 256 + tid;
        int t = lin >> 9, loc = lin & 511;
        int r = loc >> 3, p = loc & 7;
        const __nv_bfloat16* src = ((t & 1) ? ql : qh) + rowoff0
            + (size_t)(0 + r) * rstr + ((t < 2) ? DM : 2 * DM) + p * 8;
        cpa16(stg0 + t * ATILEB + r * AROWB + p * 16, src);
    }
    asm volatile("cp.async.commit_group;" ::: "memory");
    asm volatile("cp.async.wait_group 0;" ::: "memory");
    __syncthreads();

    uint32_t qfh[4][4], qfl[4][4];
    {
        uint32_t qaddr = ((w * 16 + (lane & 15)) * AROWB) + (lane >> 4) * 16;
#pragma unroll
        for (int ks = 0; ks < 4; ks++) {
            ldsm_x4(qfh[ks], Qh_s + qaddr + ks * 32);
            ldsm_x4(qfl[ks], Ql_s + qaddr + ks * 32);
        }
    }

    float oacc[8][4];
#pragma unroll
    for (int nt = 0; nt < 8; nt++)
#pragma unroll
        for (int i = 0; i < 4; i++) oacc[nt][i] = 0.f;
    float l0 = 0.f, l1 = 0.f;

    const int q0 = Qb * 128 + w * 16 + (lane >> 2);
    const int lim0 = q0 + WIN, lim1 = q0 + 8 + WIN;
    const int limw = Qb * 128 + w * 16 + 15 + WIN;
    const uint32_t kfoff = ((lane & 7) * AROWB) + ((lane >> 3) & 1) * 16;
    const uint32_t vfoff = ((lane & 15) * AROWB);

    for (int c = 0; c < nch; c++) {
        if (c > 0) {
            asm volatile("cp.async.wait_group 0;" ::: "memory");
            __syncthreads();
        }
        if (c + 1 < nch) {
            uint32_t stg = stg0 + ((c + 1) & 1) * ASTGB;
#pragma unroll
            for (int i = 0; i < 8; i++) {
                int lin = i * 256 + tid;
                int t = lin >> 9, loc = lin & 511;
                int r = loc >> 3, p = loc & 7;
                const __nv_bfloat16* src = ((t & 1) ? ql : qh) + rowoff0
                    + (size_t)((c + 1) * 64 + r) * rstr + ((t < 2) ? DM : 2 * DM) + p * 8;
                cpa16(stg + t * ATILEB + r * AROWB + p * 16, src);
            }
        }
        asm volatile("cp.async.commit_group;" ::: "memory");

        if (c * 64 > limw) continue;

        const uint32_t stg = stg0 + (c & 1) * ASTGB;
        const uint32_t Kh_s = stg, Kl_s = stg + ATILEB;
        const uint32_t Vh_s = stg + 2 * ATILEB, Vl_s = stg + 3 * ATILEB;

        float sacc[8][4];
#pragma unroll
        for (int nt = 0; nt < 8; nt++)
#pragma unroll
            for (int i = 0; i < 4; i++) sacc[nt][i] = 0.f;
#pragma unroll
        for (int ks = 0; ks < 4; ks++) {
#pragma unroll
            for (int nt = 0; nt < 8; nt++) {
                uint32_t kh[2], kl[2];
                uint32_t off = nt * 8 * AROWB + kfoff + ks * 32;
                ldsm_x2(kh, Kh_s + off);
                ldsm_x2(kl, Kl_s + off);
                mma16816(sacc[nt], qfh[ks], kh);
                mma16816(sacc[nt], qfh[ks], kl);
                mma16816(sacc[nt], qfl[ks], kh);
            }
        }

        const float scale = 0.125f;
        const bool domask = (c >= 2 * Qb + 1);
        const int jb = c * 64 + 2 * (lane & 3);
#pragma unroll
        for (int nt = 0; nt < 8; nt++) {
            int j0 = jb + nt * 8, j1 = j0 + 1;
            float s0 = sacc[nt][0] * scale, s1 = sacc[nt][1] * scale;
            float s2 = sacc[nt][2] * scale, s3 = sacc[nt][3] * scale;
            if (domask) {
                if (j0 > lim0) s0 = -1e30f;
                if (j1 > lim0) s1 = -1e30f;
                if (j0 > lim1) s2 = -1e30f;
                if (j1 > lim1) s3 = -1e30f;
            }
            float p0 = __expf(s0), p1 = __expf(s1);
            float p2 = __expf(s2), p3 = __expf(s3);
            sacc[nt][0] = p0; sacc[nt][1] = p1; sacc[nt][2] = p2; sacc[nt][3] = p3;
            l0 += p0 + p1; l1 += p2 + p3;
        }

#pragma unroll
        for (int kk = 0; kk < 4; kk++) {
            uint32_t pah[4], pal[4];
            psplit2(sacc[2*kk][0],   sacc[2*kk][1],   pah[0], pal[0]);
            psplit2(sacc[2*kk][2],   sacc[2*kk][3],   pah[1], pal[1]);
            psplit2(sacc[2*kk+1][0], sacc[2*kk+1][1], pah[2], pal[2]);
            psplit2(sacc[2*kk+1][2], sacc[2*kk+1][3], pah[3], pal[3]);
#pragma unroll
            for (int nt = 0; nt < 8; nt++) {
                uint32_t vh[2], vl[2];
                uint32_t off = kk * 16 * AROWB + vfoff + nt * 16;
                ldsm_x2t(vh, Vh_s + off);
                ldsm_x2t(vl, Vl_s + off);
                mma16816(oacc[nt], pah, vh);
                mma16816(oacc[nt], pah, vl);
                mma16816(oacc[nt], pal, vh);
            }
        }
    }

    l0 += __shfl_xor_sync(~0u, l0, 1); l0 += __shfl_xor_sync(~0u, l0, 2);
    l1 += __shfl_xor_sync(~0u, l1, 1); l1 += __shfl_xor_sync(~0u, l1, 2);
    float inv0 = 1.0f / l0, inv1 = 1.0f / l1;
    size_t orow0 = (size_t)(b * SEQ + q0) * DM + h * HD;
    size_t orow1 = orow0 + (size_t)8 * DM;
    int cbase = 2 * (lane & 3);
#pragma unroll
    for (int nt = 0; nt < 8; nt++) {
        int col = cbase + nt * 8;
        uint32_t hi, lo;
        psplit2(oacc[nt][0] * inv0, oacc[nt][1] * inv0, hi, lo);
        *(uint32_t*)(ah + orow0 + col) = hi;
        *(uint32_t*)(al + orow0 + col) = lo;
        psplit2(oacc[nt][2] * inv1, oacc[nt][3] * inv1, hi, lo);
        *(uint32_t*)(ah + orow1 + col) = hi;
        *(uint32_t*)(al + orow1 + col) = lo;
    }
}

// ======================= LayerNorm(resid + delta) -> fp32 + hi/lo =======================
__global__ void __launch_bounds__(256)
k_ln(const float* __restrict__ resid, const float* __restrict__ delta,
     const float* __restrict__ gamma, const float* __restrict__ beta,
     float* __restrict__ out, __nv_bfloat16* __restrict__ oh, __nv_bfloat16* __restrict__ ol)
{
    __shared__ float red[8];
    const int row = blockIdx.x;
    const int t = threadIdx.x;
    const float* rp = resid + (size_t)row * DM;
    const float* dp = delta + (size_t)row * DM;

    float4 rv = *(const float4*)(rp + t * 4);
    float4 dv = *(const float4*)(dp + t * 4);
    float v[4] = {rv.x + dv.x, rv.y + dv.y, rv.z + dv.z, rv.w + dv.w};

    float s = v[0] + v[1] + v[2] + v[3];
#pragma unroll
    for (int off = 16; off; off >>= 1) s += __shfl_xor_sync(~0u, s, off);
    if ((t & 31) == 0) red[t >> 5] = s;
    __syncthreads();
    if (t < 8) {
        float x = red[t];
#pragma unroll
        for (int off = 4; off; off >>= 1) x += __shfl_xor_sync(0xffu, x, off);
        if (t == 0) red[0] = x;
    }
    __syncthreads();
    float mu = red[0] * (1.0f / DM);
    __syncthreads();

    float vs = 0.f;
#pragma unroll
    for (int i = 0; i < 4; i++) { float d = v[i] - mu; vs += d * d; }
#pragma unroll
    for (int off = 16; off; off >>= 1) vs += __shfl_xor_sync(~0u, vs, off);
    if ((t & 31) == 0) red[t >> 5] = vs;
    __syncthreads();
    if (t < 8) {
        float x = red[t];
#pragma unroll
        for (int off = 4; off; off >>= 1) x += __shfl_xor_sync(0xffu, x, off);
        if (t == 0) red[0] = x;
    }
    __syncthreads();
    float rstd = rsqrtf(red[0] * (1.0f / DM) + 1e-5f);

    float4 g4 = *(const float4*)(gamma + t * 4);
    float4 b4 = *(const float4*)(beta  + t * 4);
    float w[4];
    w[0] = (v[0] - mu) * rstd * g4.x + b4.x;
    w[1] = (v[1] - mu) * rstd * g4.y + b4.y;
    w[2] = (v[2] - mu) * rstd * g4.z + b4.z;
    w[3] = (v[3] - mu) * rstd * g4.w + b4.w;
    float4 wf = {w[0], w[1], w[2], w[3]};
    *(float4*)(out + (size_t)row * DM + t * 4) = wf;
    split4(w, oh + (size_t)row * DM + t * 4, ol + (size_t)row * DM + t * 4);
}

// ======================= host driver =======================
extern "C" void kernel_launch(void* const* d_in, const int* in_sizes, int n_in,
                              void* d_out, int out_size)
{
    const float* x    = (const float*)d_in[0];
    const float* Wqkv = (const float*)d_in[1];
    const float* bqkv = (const float*)d_in[2];
    const float* Wo   = (const float*)d_in[3];
    const float* bo   = (const float*)d_in[4];
    const float* W1   = (const float*)d_in[5];
    const float* b1   = (const float*)d_in[6];
    const float* W2   = (const float*)d_in[7];
    const float* b2   = (const float*)d_in[8];
    const float* g1   = (const float*)d_in[9];
    const float* be1  = (const float*)d_in[10];
    const float* g2   = (const float*)d_in[11];
    const float* be2  = (const float*)d_in[12];
    float* out = (float*)d_out;

    float *p_xb, *p_delta;
    __nv_bfloat16 *p_xh, *p_xl, *p_qkvh, *p_qkvl, *p_ah, *p_al, *p_fh, *p_fl;
    __nv_bfloat16 *p_wqh, *p_wql, *p_woh, *p_wol, *p_w1h, *p_w1l, *p_w2h, *p_w2l;
    cudaGetSymbolAddress((void**)&p_xb,  g_xb);
    cudaGetSymbolAddress((void**)&p_delta, g_delta);
    cudaGetSymbolAddress((void**)&p_xh,  g_xh);
    cudaGetSymbolAddress((void**)&p_xl,  g_xl);
    cudaGetSymbolAddress((void**)&p_qkvh, g_qkvh);
    cudaGetSymbolAddress((void**)&p_qkvl, g_qkvl);
    cudaGetSymbolAddress((void**)&p_ah,  g_ah);
    cudaGetSymbolAddress((void**)&p_al,  g_al);
    cudaGetSymbolAddress((void**)&p_fh,  g_fh);
    cudaGetSymbolAddress((void**)&p_fl,  g_fl);
    cudaGetSymbolAddress((void**)&p_wqh, g_wqh);
    cudaGetSymbolAddress((void**)&p_wql, g_wql);
    cudaGetSymbolAddress((void**)&p_woh, g_woh);
    cudaGetSymbolAddress((void**)&p_wol, g_wol);
    cudaGetSymbolAddress((void**)&p_w1h, g_w1h);
    cudaGetSymbolAddress((void**)&p_w1l, g_w1l);
    cudaGetSymbolAddress((void**)&p_w2h, g_w2h);
    cudaGetSymbolAddress((void**)&p_w2l, g_w2l);

    cudaFuncSetAttribute(k_tgemm<0,0>, cudaFuncAttributeMaxDynamicSharedMemorySize, TG_SMEM);
    cudaFuncSetAttribute(k_tgemm<0,1>, cudaFuncAttributeMaxDynamicSharedMemorySize, TG_SMEM);
    cudaFuncSetAttribute(k_tgemm<1,1>, cudaFuncAttributeMaxDynamicSharedMemorySize, TG_SMEM);
    cudaFuncSetAttribute(k_attn, cudaFuncAttributeMaxDynamicSharedMemorySize, ATT_SMEM);

    {
        int ntot = (NL * 3 * DM * DM + NL * DM * DM + NL * DFF * DM + NL * DM * DFF) / 4;
        k_split_all<<<(ntot + 255) / 256, 256>>>(Wqkv, Wo, W1, W2,
            p_wqh, p_wql, p_woh, p_wol, p_w1h, p_w1l, p_w2h, p_w2l);
    }

    const int nElem = MTOT * DM;
    k_in<<<(nElem + 255) / 256, 256>>>(x, p_xb, p_xh, p_xl);

    for (int l = 0; l < NL; l++) {
        k_tgemm<0,1><<<dim3(3 * DM / 128, MTOT / 256), 512, TG_SMEM>>>(
            p_xh, p_xl,
            p_wqh + (size_t)l * 3 * DM * DM, p_wql + (size_t)l * 3 * DM * DM,
            bqkv + (size_t)l * 3 * DM,
            nullptr, p_qkvh, p_qkvl, MTOT, 3 * DM, DM);

        k_attn<<<dim3(SEQ / 128, NH, BATCH), 256, ATT_SMEM>>>(p_qkvh, p_qkvl, p_ah, p_al);

        k_tgemm<0,0><<<dim3(DM / 128, MTOT / 256), 512, TG_SMEM>>>(
            p_ah, p_al,
            p_woh + (size_t)l * DM * DM, p_wol + (size_t)l * DM * DM,
            bo + (size_t)l * DM,
            p_delta, nullptr, nullptr, MTOT, DM, DM);

        k_ln<<<MTOT, 256>>>(p_xb, p_delta, g1 + (size_t)l * DM, be1 + (size_t)l * DM,
                            p_xb, p_xh, p_xl);

        k_tgemm<1,1><<<dim3(DFF / 128, MTOT / 256), 512, TG_SMEM>>>(
            p_xh, p_xl,
            p_w1h + (size_t)l * DFF * DM, p_w1l + (size_t)l * DFF * DM,
            b1 + (size_t)l * DFF,
            nullptr, p_fh, p_fl, MTOT, DFF, DM);

        k_tgemm<0,0><<<dim3(DM / 128, MTOT / 256), 512, TG_SMEM>>>(
            p_fh, p_fl,
            p_w2h + (size_t)l * DM * DFF, p_w2l + (size_t)l * DM * DFF,
            b2 + (size_t)l * DM,
            p_delta, nullptr, nullptr, MTOT, DM, DFF);

        k_ln<<<MTOT, 256>>>(p_xb, p_delta, g2 + (size_t)l * DM, be2 + (size_t)l * DM,
                            p_xb, p_xh, p_xl);
    }

    k_out<<<(nElem + 255) / 256, 256>>>(p_xb, out);
}

// round 16
// speedup vs baseline: 1.3885x; 1.3885x over previous
#include <cuda_runtime.h>
#include <cuda_bf16.h>
#include <cuda_fp16.h>
#include <cstdint>

#define SEQ   1024
#define BATCH 4
#define DM    1024
#define NH    16
#define HD    64
#define DFF   4096
#define NL    4
#define WIN   64
#define MTOT  (SEQ*BATCH)

// ======================= PTX helpers (sm_80+ features only) =======================
__device__ __forceinline__ uint32_t smem_to_u32(const void* p) {
    uint32_t a;
    asm("{ .reg .u64 t; cvta.to.shared.u64 t, %1; cvt.u32.u64 %0, t; }" : "=r"(a) : "l"(p));
    return a;
}
__device__ __forceinline__ void cpa16(uint32_t smem, const void* gmem) {
    asm volatile("cp.async.cg.shared.global [%0], [%1], 16;" :: "r"(smem), "l"(gmem) : "memory");
}
__device__ __forceinline__ void ldsm_x4(uint32_t* r, uint32_t addr) {
    asm volatile("ldmatrix.sync.aligned.m8n8.x4.shared.b16 {%0,%1,%2,%3}, [%4];"
        : "=r"(r[0]), "=r"(r[1]), "=r"(r[2]), "=r"(r[3]) : "r"(addr));
}
__device__ __forceinline__ void ldsm_x2(uint32_t* r, uint32_t addr) {
    asm volatile("ldmatrix.sync.aligned.m8n8.x2.shared.b16 {%0,%1}, [%2];"
        : "=r"(r[0]), "=r"(r[1]) : "r"(addr));
}
__device__ __forceinline__ void ldsm_x2t(uint32_t* r, uint32_t addr) {
    asm volatile("ldmatrix.sync.aligned.m8n8.x2.trans.shared.b16 {%0,%1}, [%2];"
        : "=r"(r[0]), "=r"(r[1]) : "r"(addr));
}
// bf16 mma (attention)
__device__ __forceinline__ void mma16816(float* c, const uint32_t* a, const uint32_t* b) {
    asm volatile(
        "mma.sync.aligned.m16n8k16.row.col.f32.bf16.bf16.f32 "
        "{%0,%1,%2,%3}, {%4,%5,%6,%7}, {%8,%9}, {%0,%1,%2,%3};"
        : "+f"(c[0]), "+f"(c[1]), "+f"(c[2]), "+f"(c[3])
        : "r"(a[0]), "r"(a[1]), "r"(a[2]), "r"(a[3]), "r"(b[0]), "r"(b[1]));
}
// fp16 mma (GEMMs)
__device__ __forceinline__ void mma16816h(float* c, const uint32_t* a, const uint32_t* b) {
    asm volatile(
        "mma.sync.aligned.m16n8k16.row.col.f32.f16.f16.f32 "
        "{%0,%1,%2,%3}, {%4,%5,%6,%7}, {%8,%9}, {%0,%1,%2,%3};"
        : "+f"(c[0]), "+f"(c[1]), "+f"(c[2]), "+f"(c[3])
        : "r"(a[0]), "r"(a[1]), "r"(a[2]), "r"(a[3]), "r"(b[0]), "r"(b[1]));
}

// ======================= scratch (device globals) =======================
__device__ __align__(256) float          g_xb   [MTOT * DM];
__device__ __align__(256) __half         g_x16  [MTOT * DM];
__device__ __align__(256) __nv_bfloat16  g_qkvh [MTOT * 3 * DM];
__device__ __align__(256) __nv_bfloat16  g_qkvl [MTOT * 3 * DM];
__device__ __align__(256) __half         g_a16  [MTOT * DM];
__device__ __align__(256) float          g_delta[MTOT * DM];
__device__ __align__(256) __half         g_f16  [MTOT * DFF];
__device__ __align__(256) __half         g_wqh  [NL * 3 * DM * DM];
__device__ __align__(256) __half         g_wql  [NL * 3 * DM * DM];
__device__ __align__(256) __half         g_woh  [NL * DM * DM];
__device__ __align__(256) __half         g_wol  [NL * DM * DM];
__device__ __align__(256) __half         g_w1h  [NL * DFF * DM];
__device__ __align__(256) __half         g_w1l  [NL * DFF * DM];
__device__ __align__(256) __half         g_w2h  [NL * DM * DFF];
__device__ __align__(256) __half         g_w2l  [NL * DM * DFF];

__device__ __forceinline__ void psplit2(float p0, float p1, uint32_t& hi, uint32_t& lo) {
    __nv_bfloat16 h0 = __float2bfloat16(p0), h1 = __float2bfloat16(p1);
    __nv_bfloat16 r0 = __float2bfloat16(p0 - __bfloat162float(h0));
    __nv_bfloat16 r1 = __float2bfloat16(p1 - __bfloat162float(h1));
    __nv_bfloat162 H; H.x = h0; H.y = h1;
    __nv_bfloat162 L; L.x = r0; L.y = r1;
    hi = *(uint32_t*)&H; lo = *(uint32_t*)&L;
}

// ======================= fused weight split (float -> fp16 hi/lo) =======================
__global__ void k_split_all(const float* __restrict__ Wqkv, const float* __restrict__ Wo,
                            const float* __restrict__ W1,   const float* __restrict__ W2,
                            __half* wqh, __half* wql, __half* woh, __half* wol,
                            __half* w1h, __half* w1l, __half* w2h, __half* w2l)
{
    const int N0 = NL * 3 * DM * DM / 4;
    const int N1 = NL * DM * DM / 4;
    const int N2 = NL * DFF * DM / 4;
    const int N3 = NL * DM * DFF / 4;
    int i = blockIdx.x * blockDim.x + threadIdx.x;
    const float* s; __half *h, *l; int j;
    if (i < N0)                { s = Wqkv; h = wqh; l = wql; j = i; }
    else if (i < N0+N1)        { s = Wo;   h = woh; l = wol; j = i - N0; }
    else if (i < N0+N1+N2)     { s = W1;   h = w1h; l = w1l; j = i - N0 - N1; }
    else if (i < N0+N1+N2+N3)  { s = W2;   h = w2h; l = w2l; j = i - N0 - N1 - N2; }
    else return;
    float v[4];
    *(float4*)v = *(const float4*)(s + (size_t)j * 4);
    __half h0 = __float2half(v[0]), h1 = __float2half(v[1]);
    __half h2 = __float2half(v[2]), h3 = __float2half(v[3]);
    __half l0 = __float2half(v[0] - __half2float(h0));
    __half l1 = __float2half(v[1] - __half2float(h1));
    __half l2 = __float2half(v[2] - __half2float(h2));
    __half l3 = __float2half(v[3] - __half2float(h3));
    __half2 H0; H0.x = h0; H0.y = h1;
    __half2 H1; H1.x = h2; H1.y = h3;
    __half2 L0; L0.x = l0; L0.y = l1;
    __half2 L1; L1.x = l2; L1.y = l3;
    *(__half2*)(h + (size_t)j * 4)     = H0;
    *(__half2*)(h + (size_t)j * 4 + 2) = H1;
    *(__half2*)(l + (size_t)j * 4)     = L0;
    *(__half2*)(l + (size_t)j * 4 + 2) = L1;
}

// ======================= layout transposes =======================
__global__ void k_in(const float* __restrict__ x, float* __restrict__ xb,
                     __half* __restrict__ x16) {
    int idx = blockIdx.x * blockDim.x + threadIdx.x;
    if (idx >= MTOT * DM) return;
    int kcol = idx % DM;
    int row  = idx / DM;
    int b = row / SEQ, s = row % SEQ;
    float v = x[((size_t)(s * BATCH + b)) * DM + kcol];
    xb[idx] = v;
    x16[idx] = __float2half(v);
}

__global__ void k_out(const float* __restrict__ xb, float* __restrict__ out) {
    int idx = blockIdx.x * blockDim.x + threadIdx.x;
    if (idx >= MTOT * DM) return;
    int kcol = idx % DM;
    int r    = idx / DM;
    int b = r % BATCH, s = r / BATCH;
    out[idx] = xb[((size_t)(b * SEQ + s)) * DM + kcol];
}

// ======================= fp16 HMMA GEMM: 256x128 tile, 2-term split =======================
// C[M,N] = A[M,K] * (Bh+Bl)[N,K]^T + bias. A single fp16, B fp16 hi/lo.
// OMODE: 0 = fp32 out, 1 = bf16 hi/lo out (for attention), 2 = fp16 out.
#define PAD    72
#define A16_B  (256 * PAD * 2)        // 36864
#define BH_B   (128 * PAD * 2)        // 18432
#define STG_B  (A16_B + 2 * BH_B)     // 73728
#define TG_SMEM (2 * STG_B)           // 147456

template<int RELU, int OMODE>
__global__ void __launch_bounds__(256, 1)
k_tgemm(const __half* __restrict__ A,
        const __half* __restrict__ Bh, const __half* __restrict__ Bl,
        const float* __restrict__ bias,
        float* __restrict__ Cf, __nv_bfloat16* __restrict__ Ch, __nv_bfloat16* __restrict__ Cl,
        __half* __restrict__ C16,
        int M, int N, int K)
{
    extern __shared__ char dsm[];
    const uint32_t sbase = smem_to_u32(dsm);
    const int tid  = threadIdx.x;
    const int lane = tid & 31;
    const int wid  = tid >> 5;
    const int wm   = wid >> 1;          // 0..3 (64-row slab)
    const int wn   = wid & 1;           // 0..1 (64-col slab)
    const int m0 = blockIdx.y * 256;
    const int n0 = blockIdx.x * 128;
    const int nch = K >> 6;

    float acc[4][8][4];
#pragma unroll
    for (int mt = 0; mt < 4; mt++)
#pragma unroll
        for (int nt = 0; nt < 8; nt++)
#pragma unroll
            for (int i = 0; i < 4; i++) acc[mt][nt][i] = 0.f;

    const uint32_t aoff = ((wm * 64 + (lane & 15)) * PAD + (lane >> 4) * 8) * 2;
    const uint32_t boff = ((wn * 64 + (lane & 7)) * PAD + ((lane >> 3) & 1) * 8) * 2;

    // 4096 x 16B pieces per chunk, 16 per thread
    auto load_chunk = [&](int cc, int s) {
        uint32_t stg = sbase + s * STG_B;
#pragma unroll
        for (int i = 0; i < 16; i++) {
            int idx = tid + i * 256;
            if (idx < 2048) {                       // A tile (256 rows)
                int r = idx >> 3, c = idx & 7;
                cpa16(stg + r * (PAD * 2) + c * 16,
                      A + (size_t)(m0 + r) * K + cc * 64 + c * 8);
            } else {                                // B tiles (hi, lo; 128 rows each)
                int j = idx - 2048;
                int t = j >> 10, loc = j & 1023;
                int r = loc >> 3, c = loc & 7;
                cpa16(stg + A16_B + t * BH_B + r * (PAD * 2) + c * 16,
                      (t ? Bl : Bh) + (size_t)(n0 + r) * K + cc * 64 + c * 8);
            }
        }
    };

    load_chunk(0, 0);
    asm volatile("cp.async.commit_group;" ::: "memory");

    for (int cch = 0; cch < nch; cch++) {
        __syncthreads();
        if (cch + 1 < nch) load_chunk(cch + 1, (cch + 1) & 1);
        asm volatile("cp.async.commit_group;" ::: "memory");
        asm volatile("cp.async.wait_group 1;" ::: "memory");
        __syncthreads();

        const uint32_t stg = sbase + (cch & 1) * STG_B;
        const uint32_t A_s = stg;
        const uint32_t Bh_s = stg + A16_B, Bl_s = stg + A16_B + BH_B;

#pragma unroll
        for (int ks = 0; ks < 4; ks++) {
            uint32_t bh[8][2], bl[8][2];
#pragma unroll
            for (int nt = 0; nt < 8; nt++) {
                uint32_t off = boff + (nt * 8 * PAD + ks * 16) * 2;
                ldsm_x2(bh[nt], Bh_s + off);
                ldsm_x2(bl[nt], Bl_s + off);
            }
#pragma unroll
            for (int mt = 0; mt < 4; mt++) {
                uint32_t ah[4];
                ldsm_x4(ah, A_s + aoff + (mt * 16 * PAD + ks * 16) * 2);
#pragma unroll
                for (int nt = 0; nt < 8; nt++) {
                    mma16816h(acc[mt][nt], ah, bh[nt]);
                    mma16816h(acc[mt][nt], ah, bl[nt]);
                }
            }
        }
    }

    const int r0 = m0 + wm * 64 + (lane >> 2);
    const int c0 = n0 + wn * 64 + 2 * (lane & 3);
#pragma unroll
    for (int mt = 0; mt < 4; mt++) {
#pragma unroll
        for (int nt = 0; nt < 8; nt++) {
            int col = c0 + nt * 8;
            float b0 = bias[col], b1 = bias[col + 1];
#pragma unroll
            for (int half = 0; half < 2; half++) {
                int row = r0 + mt * 16 + half * 8;
                float v0 = acc[mt][nt][2 * half + 0] + b0;
                float v1 = acc[mt][nt][2 * half + 1] + b1;
                if (RELU) { v0 = fmaxf(v0, 0.f); v1 = fmaxf(v1, 0.f); }
                size_t off = (size_t)row * N + col;
                if (OMODE == 0) {
                    float2 w = {v0, v1};
                    *(float2*)(Cf + off) = w;
                } else if (OMODE == 1) {
                    uint32_t hi, lo;
                    psplit2(v0, v1, hi, lo);
                    *(uint32_t*)(Ch + off) = hi;
                    *(uint32_t*)(Cl + off) = lo;
                } else {
                    *(__half2*)(C16 + off) = __floats2half2_rn(v0, v1);
                }
            }
        }
    }
}

// ======================= HMMA banded flash attention (bf16 3-term, no running max) =======================
#define AP     72
#define AROWB  (AP * 2)
#define QTILEB (128 * AROWB)
#define ATILEB (64 * AROWB)
#define ASTGB  (4 * ATILEB)
#define ATT_SMEM (2 * QTILEB + 2 * ASTGB)

__global__ void __launch_bounds__(256, 1)
k_attn(const __nv_bfloat16* __restrict__ qh, const __nv_bfloat16* __restrict__ ql,
       __half* __restrict__ a16)
{
    extern __shared__ char asm_[];
    const uint32_t sbase = smem_to_u32(asm_);
    const uint32_t Qh_s = sbase, Ql_s = sbase + QTILEB;
    const uint32_t stg0 = sbase + 2 * QTILEB;

    const int tid = threadIdx.x;
    const int lane = tid & 31;
    const int w = tid >> 5;
    const int Qb = (gridDim.x - 1) - blockIdx.x;     // heavy tiles first
    const int h = blockIdx.y, b = blockIdx.z;
    const int nch = min(16, 2 * Qb + 3);
    const size_t rstr = 3 * DM;
    const size_t rowoff0 = (size_t)(b * SEQ) * rstr + h * HD;

#pragma unroll
    for (int i = 0; i < 8; i++) {
        int lin = i * 256 + tid;
        int hl = lin >> 10, loc = lin & 1023;
        int r = loc >> 3, p = loc & 7;
        const __nv_bfloat16* src = (hl ? ql : qh) + rowoff0 + (size_t)(Qb * 128 + r) * rstr + p * 8;
        cpa16((hl ? Ql_s : Qh_s) + r * AROWB + p * 16, src);
    }
#pragma unroll
    for (int i = 0; i < 8; i++) {
        int lin = i * 256 + tid;
        int t = lin >> 9, loc = lin & 511;
        int r = loc >> 3, p = loc & 7;
        const __nv_bfloat16* src = ((t & 1) ? ql : qh) + rowoff0
            + (size_t)(0 + r) * rstr + ((t < 2) ? DM : 2 * DM) + p * 8;
        cpa16(stg0 + t * ATILEB + r * AROWB + p * 16, src);
    }
    asm volatile("cp.async.commit_group;" ::: "memory");
    asm volatile("cp.async.wait_group 0;" ::: "memory");
    __syncthreads();

    uint32_t qfh[4][4], qfl[4][4];
    {
        uint32_t qaddr = ((w * 16 + (lane & 15)) * AROWB) + (lane >> 4) * 16;
#pragma unroll
        for (int ks = 0; ks < 4; ks++) {
            ldsm_x4(qfh[ks], Qh_s + qaddr + ks * 32);
            ldsm_x4(qfl[ks], Ql_s + qaddr + ks * 32);
        }
    }

    float oacc[8][4];
#pragma unroll
    for (int nt = 0; nt < 8; nt++)
#pragma unroll
        for (int i = 0; i < 4; i++) oacc[nt][i] = 0.f;
    float l0 = 0.f, l1 = 0.f;

    const int q0 = Qb * 128 + w * 16 + (lane >> 2);
    const int lim0 = q0 + WIN, lim1 = q0 + 8 + WIN;
    const int limw = Qb * 128 + w * 16 + 15 + WIN;
    const uint32_t kfoff = ((lane & 7) * AROWB) + ((lane >> 3) & 1) * 16;
    const uint32_t vfoff = ((lane & 15) * AROWB);

    for (int c = 0; c < nch; c++) {
        if (c > 0) {
            asm volatile("cp.async.wait_group 0;" ::: "memory");
            __syncthreads();
        }
        if (c + 1 < nch) {
            uint32_t stg = stg0 + ((c + 1) & 1) * ASTGB;
#pragma unroll
            for (int i = 0; i < 8; i++) {
                int lin = i * 256 + tid;
                int t = lin >> 9, loc = lin & 511;
                int r = loc >> 3, p = loc & 7;
                const __nv_bfloat16* src = ((t & 1) ? ql : qh) + rowoff0
                    + (size_t)((c + 1) * 64 + r) * rstr + ((t < 2) ? DM : 2 * DM) + p * 8;
                cpa16(stg + t * ATILEB + r * AROWB + p * 16, src);
            }
        }
        asm volatile("cp.async.commit_group;" ::: "memory");

        if (c * 64 > limw) continue;

        const uint32_t stg = stg0 + (c & 1) * ASTGB;
        const uint32_t Kh_s = stg, Kl_s = stg + ATILEB;
        const uint32_t Vh_s = stg + 2 * ATILEB, Vl_s = stg + 3 * ATILEB;

        float sacc[8][4];
#pragma unroll
        for (int nt = 0; nt < 8; nt++)
#pragma unroll
            for (int i = 0; i < 4; i++) sacc[nt][i] = 0.f;
#pragma unroll
        for (int ks = 0; ks < 4; ks++) {
#pragma unroll
            for (int nt = 0; nt < 8; nt++) {
                uint32_t kh[2], kl[2];
                uint32_t off = nt * 8 * AROWB + kfoff + ks * 32;
                ldsm_x2(kh, Kh_s + off);
                ldsm_x2(kl, Kl_s + off);
                mma16816(sacc[nt], qfh[ks], kh);
                mma16816(sacc[nt], qfh[ks], kl);
                mma16816(sacc[nt], qfl[ks], kh);
            }
        }

        const float scale = 0.125f;
        const bool domask = (c >= 2 * Qb + 1);
        const int jb = c * 64 + 2 * (lane & 3);
#pragma unroll
        for (int nt = 0; nt < 8; nt++) {
            int j0 = jb + nt * 8, j1 = j0 + 1;
            float s0 = sacc[nt][0] * scale, s1 = sacc[nt][1] * scale;
            float s2 = sacc[nt][2] * scale, s3 = sacc[nt][3] * scale;
            if (domask) {
                if (j0 > lim0) s0 = -1e30f;
                if (j1 > lim0) s1 = -1e30f;
                if (j0 > lim1) s2 = -1e30f;
                if (j1 > lim1) s3 = -1e30f;
            }
            float p0 = __expf(s0), p1 = __expf(s1);
            float p2 = __expf(s2), p3 = __expf(s3);
            sacc[nt][0] = p0; sacc[nt][1] = p1; sacc[nt][2] = p2; sacc[nt][3] = p3;
            l0 += p0 + p1; l1 += p2 + p3;
        }

#pragma unroll
        for (int kk = 0; kk < 4; kk++) {
            uint32_t pah[4], pal[4];
            psplit2(sacc[2*kk][0],   sacc[2*kk][1],   pah[0], pal[0]);
            psplit2(sacc[2*kk][2],   sacc[2*kk][3],   pah[1], pal[1]);
            psplit2(sacc[2*kk+1][0], sacc[2*kk+1][1], pah[2], pal[2]);
            psplit2(sacc[2*kk+1][2], sacc[2*kk+1][3], pah[3], pal[3]);
#pragma unroll
            for (int nt = 0; nt < 8; nt++) {
                uint32_t vh[2], vl[2];
                uint32_t off = kk * 16 * AROWB + vfoff + nt * 16;
                ldsm_x2t(vh, Vh_s + off);
                ldsm_x2t(vl, Vl_s + off);
                mma16816(oacc[nt], pah, vh);
                mma16816(oacc[nt], pah, vl);
                mma16816(oacc[nt], pal, vh);
            }
        }
    }

    l0 += __shfl_xor_sync(~0u, l0, 1); l0 += __shfl_xor_sync(~0u, l0, 2);
    l1 += __shfl_xor_sync(~0u, l1, 1); l1 += __shfl_xor_sync(~0u, l1, 2);
    float inv0 = 1.0f / l0, inv1 = 1.0f / l1;
    size_t orow0 = (size_t)(b * SEQ + q0) * DM + h * HD;
    size_t orow1 = orow0 + (size_t)8 * DM;
    int cbase = 2 * (lane & 3);
#pragma unroll
    for (int nt = 0; nt < 8; nt++) {
        int col = cbase + nt * 8;
        *(__half2*)(a16 + orow0 + col) = __floats2half2_rn(oacc[nt][0] * inv0, oacc[nt][1] * inv0);
        *(__half2*)(a16 + orow1 + col) = __floats2half2_rn(oacc[nt][2] * inv1, oacc[nt][3] * inv1);
    }
}

// ======================= LayerNorm(resid + delta) -> fp32 + fp16 =======================
__global__ void __launch_bounds__(256)
k_ln(const float* __restrict__ resid, const float* __restrict__ delta,
     const float* __restrict__ gamma, const float* __restrict__ beta,
     float* __restrict__ out, __half* __restrict__ o16)
{
    __shared__ float red[8];
    const int row = blockIdx.x;
    const int t = threadIdx.x;
    const float* rp = resid + (size_t)row * DM;
    const float* dp = delta + (size_t)row * DM;

    float4 rv = *(const float4*)(rp + t * 4);
    float4 dv = *(const float4*)(dp + t * 4);
    float v[4] = {rv.x + dv.x, rv.y + dv.y, rv.z + dv.z, rv.w + dv.w};

    float s = v[0] + v[1] + v[2] + v[3];
#pragma unroll
    for (int off = 16; off; off >>= 1) s += __shfl_xor_sync(~0u, s, off);
    if ((t & 31) == 0) red[t >> 5] = s;
    __syncthreads();
    if (t < 8) {
        float x = red[t];
#pragma unroll
        for (int off = 4; off; off >>= 1) x += __shfl_xor_sync(0xffu, x, off);
        if (t == 0) red[0] = x;
    }
    __syncthreads();
    float mu = red[0] * (1.0f / DM);
    __syncthreads();

    float vs = 0.f;
#pragma unroll
    for (int i = 0; i < 4; i++) { float d = v[i] - mu; vs += d * d; }
#pragma unroll
    for (int off = 16; off; off >>= 1) vs += __shfl_xor_sync(~0u, vs, off);
    if ((t & 31) == 0) red[t >> 5] = vs;
    __syncthreads();
    if (t < 8) {
        float x = red[t];
#pragma unroll
        for (int off = 4; off; off >>= 1) x += __shfl_xor_sync(0xffu, x, off);
        if (t == 0) red[0] = x;
    }
    __syncthreads();
    float rstd = rsqrtf(red[0] * (1.0f / DM) + 1e-5f);

    float4 g4 = *(const float4*)(gamma + t * 4);
    float4 b4 = *(const float4*)(beta  + t * 4);
    float w[4];
    w[0] = (v[0] - mu) * rstd * g4.x + b4.x;
    w[1] = (v[1] - mu) * rstd * g4.y + b4.y;
    w[2] = (v[2] - mu) * rstd * g4.z + b4.z;
    w[3] = (v[3] - mu) * rstd * g4.w + b4.w;
    float4 wf = {w[0], w[1], w[2], w[3]};
    size_t o4 = (size_t)row * DM + t * 4;
    *(float4*)(out + o4) = wf;
    *(__half2*)(o16 + o4)     = __floats2half2_rn(w[0], w[1]);
    *(__half2*)(o16 + o4 + 2) = __floats2half2_rn(w[2], w[3]);
}

// ======================= host driver =======================
extern "C" void kernel_launch(void* const* d_in, const int* in_sizes, int n_in,
                              void* d_out, int out_size)
{
    const float* x    = (const float*)d_in[0];
    const float* Wqkv = (const float*)d_in[1];
    const float* bqkv = (const float*)d_in[2];
    const float* Wo   = (const float*)d_in[3];
    const float* bo   = (const float*)d_in[4];
    const float* W1   = (const float*)d_in[5];
    const float* b1   = (const float*)d_in[6];
    const float* W2   = (const float*)d_in[7];
    const float* b2   = (const float*)d_in[8];
    const float* g1   = (const float*)d_in[9];
    const float* be1  = (const float*)d_in[10];
    const float* g2   = (const float*)d_in[11];
    const float* be2  = (const float*)d_in[12];
    float* out = (float*)d_out;

    float *p_xb, *p_delta;
    __half *p_x16, *p_a16, *p_f16;
    __nv_bfloat16 *p_qkvh, *p_qkvl;
    __half *p_wqh, *p_wql, *p_woh, *p_wol, *p_w1h, *p_w1l, *p_w2h, *p_w2l;
    cudaGetSymbolAddress((void**)&p_xb,  g_xb);
    cudaGetSymbolAddress((void**)&p_delta, g_delta);
    cudaGetSymbolAddress((void**)&p_x16, g_x16);
    cudaGetSymbolAddress((void**)&p_a16, g_a16);
    cudaGetSymbolAddress((void**)&p_f16, g_f16);
    cudaGetSymbolAddress((void**)&p_qkvh, g_qkvh);
    cudaGetSymbolAddress((void**)&p_qkvl, g_qkvl);
    cudaGetSymbolAddress((void**)&p_wqh, g_wqh);
    cudaGetSymbolAddress((void**)&p_wql, g_wql);
    cudaGetSymbolAddress((void**)&p_woh, g_woh);
    cudaGetSymbolAddress((void**)&p_wol, g_wol);
    cudaGetSymbolAddress((void**)&p_w1h, g_w1h);
    cudaGetSymbolAddress((void**)&p_w1l, g_w1l);
    cudaGetSymbolAddress((void**)&p_w2h, g_w2h);
    cudaGetSymbolAddress((void**)&p_w2l, g_w2l);

    cudaFuncSetAttribute(k_tgemm<0,0>, cudaFuncAttributeMaxDynamicSharedMemorySize, TG_SMEM);
    cudaFuncSetAttribute(k_tgemm<0,1>, cudaFuncAttributeMaxDynamicSharedMemorySize, TG_SMEM);
    cudaFuncSetAttribute(k_tgemm<1,2>, cudaFuncAttributeMaxDynamicSharedMemorySize, TG_SMEM);
    cudaFuncSetAttribute(k_attn, cudaFuncAttributeMaxDynamicSharedMemorySize, ATT_SMEM);

    {
        int ntot = (NL * 3 * DM * DM + NL * DM * DM + NL * DFF * DM + NL * DM * DFF) / 4;
        k_split_all<<<(ntot + 255) / 256, 256>>>(Wqkv, Wo, W1, W2,
            p_wqh, p_wql, p_woh, p_wol, p_w1h, p_w1l, p_w2h, p_w2l);
    }

    const int nElem = MTOT * DM;
    k_in<<<(nElem + 255) / 256, 256>>>(x, p_xb, p_x16);

    for (int l = 0; l < NL; l++) {
        // QKV projection -> bf16 hi/lo for attention
        k_tgemm<0,1><<<dim3(3 * DM / 128, MTOT / 256), 256, TG_SMEM>>>(
            p_x16,
            p_wqh + (size_t)l * 3 * DM * DM, p_wql + (size_t)l * 3 * DM * DM,
            bqkv + (size_t)l * 3 * DM,
            nullptr, p_qkvh, p_qkvl, nullptr, MTOT, 3 * DM, DM);

        // attention (bf16 3-term) -> single fp16
        k_attn<<<dim3(SEQ / 128, NH, BATCH), 256, ATT_SMEM>>>(p_qkvh, p_qkvl, p_a16);

        // output projection -> fp32 delta
        k_tgemm<0,0><<<dim3(DM / 128, MTOT / 256), 256, TG_SMEM>>>(
            p_a16,
            p_woh + (size_t)l * DM * DM, p_wol + (size_t)l * DM * DM,
            bo + (size_t)l * DM,
            p_delta, nullptr, nullptr, nullptr, MTOT, DM, DM);

        k_ln<<<MTOT, 256>>>(p_xb, p_delta, g1 + (size_t)l * DM, be1 + (size_t)l * DM,
                            p_xb, p_x16);

        // FF1 + ReLU -> single fp16
        k_tgemm<1,2><<<dim3(DFF / 128, MTOT / 256), 256, TG_SMEM>>>(
            p_x16,
            p_w1h + (size_t)l * DFF * DM, p_w1l + (size_t)l * DFF * DM,
            b1 + (size_t)l * DFF,
            nullptr, nullptr, nullptr, p_f16, MTOT, DFF, DM);

        // FF2 -> fp32 delta
        k_tgemm<0,0><<<dim3(DM / 128, MTOT / 256), 256, TG_SMEM>>>(
            p_f16,
            p_w2h + (size_t)l * DM * DFF, p_w2l + (size_t)l * DM * DFF,
            b2 + (size_t)l * DM,
            p_delta, nullptr, nullptr, nullptr, MTOT, DM, DFF);

        k_ln<<<MTOT, 256>>>(p_xb, p_delta, g2 + (size_t)l * DM, be2 + (size_t)l * DM,
                            p_xb, p_x16);
    }

    k_out<<<(nElem + 255) / 256, 256>>>(p_xb, out);
}

// round 17
// speedup vs baseline: 1.4381x; 1.0357x over previous
#include <cuda_runtime.h>
#include <cuda_bf16.h>
#include <cuda_fp16.h>
#include <cstdint>

#define SEQ   1024
#define BATCH 4
#define DM    1024
#define NH    16
#define HD    64
#define DFF   4096
#define NL    4
#define WIN   64
#define MTOT  (SEQ*BATCH)

// ======================= PTX helpers (sm_80+ features only) =======================
__device__ __forceinline__ uint32_t smem_to_u32(const void* p) {
    uint32_t a;
    asm("{ .reg .u64 t; cvta.to.shared.u64 t, %1; cvt.u32.u64 %0, t; }" : "=r"(a) : "l"(p));
    return a;
}
__device__ __forceinline__ void cpa16(uint32_t smem, const void* gmem) {
    asm volatile("cp.async.cg.shared.global [%0], [%1], 16;" :: "r"(smem), "l"(gmem) : "memory");
}
__device__ __forceinline__ void ldsm_x4(uint32_t* r, uint32_t addr) {
    asm volatile("ldmatrix.sync.aligned.m8n8.x4.shared.b16 {%0,%1,%2,%3}, [%4];"
        : "=r"(r[0]), "=r"(r[1]), "=r"(r[2]), "=r"(r[3]) : "r"(addr));
}
__device__ __forceinline__ void ldsm_x2(uint32_t* r, uint32_t addr) {
    asm volatile("ldmatrix.sync.aligned.m8n8.x2.shared.b16 {%0,%1}, [%2];"
        : "=r"(r[0]), "=r"(r[1]) : "r"(addr));
}
__device__ __forceinline__ void ldsm_x2t(uint32_t* r, uint32_t addr) {
    asm volatile("ldmatrix.sync.aligned.m8n8.x2.trans.shared.b16 {%0,%1}, [%2];"
        : "=r"(r[0]), "=r"(r[1]) : "r"(addr));
}
// fp16 mma
__device__ __forceinline__ void mma16816h(float* c, const uint32_t* a, const uint32_t* b) {
    asm volatile(
        "mma.sync.aligned.m16n8k16.row.col.f32.f16.f16.f32 "
        "{%0,%1,%2,%3}, {%4,%5,%6,%7}, {%8,%9}, {%0,%1,%2,%3};"
        : "+f"(c[0]), "+f"(c[1]), "+f"(c[2]), "+f"(c[3])
        : "r"(a[0]), "r"(a[1]), "r"(a[2]), "r"(a[3]), "r"(b[0]), "r"(b[1]));
}
__device__ __forceinline__ uint32_t packh2(float a, float b) {
    __half2 h = __floats2half2_rn(a, b);
    return *(uint32_t*)&h;
}

// ======================= scratch (device globals) =======================
__device__ __align__(256) float          g_xb   [MTOT * DM];
__device__ __align__(256) __half         g_x16  [MTOT * DM];
__device__ __align__(256) __half         g_qkvh [MTOT * 3 * DM];
__device__ __align__(256) __half         g_qkvl [MTOT * 3 * DM];
__device__ __align__(256) __half         g_a16  [MTOT * DM];
__device__ __align__(256) float          g_delta[MTOT * DM];
__device__ __align__(256) __half         g_f16  [MTOT * DFF];
__device__ __align__(256) __half         g_wqh  [NL * 3 * DM * DM];
__device__ __align__(256) __half         g_wql  [NL * 3 * DM * DM];
__device__ __align__(256) __half         g_woh  [NL * DM * DM];
__device__ __align__(256) __half         g_wol  [NL * DM * DM];
__device__ __align__(256) __half         g_w1h  [NL * DFF * DM];
__device__ __align__(256) __half         g_w1l  [NL * DFF * DM];
__device__ __align__(256) __half         g_w2h  [NL * DM * DFF];
__device__ __align__(256) __half         g_w2l  [NL * DM * DFF];

// pack fp16 hi/lo pair
__device__ __forceinline__ void hsplit2(float v0, float v1, uint32_t& hi, uint32_t& lo) {
    __half h0 = __float2half(v0), h1 = __float2half(v1);
    __half l0 = __float2half(v0 - __half2float(h0));
    __half l1 = __float2half(v1 - __half2float(h1));
    __half2 H; H.x = h0; H.y = h1;
    __half2 L; L.x = l0; L.y = l1;
    hi = *(uint32_t*)&H; lo = *(uint32_t*)&L;
}

// ======================= fused weight split (float -> fp16 hi/lo) =======================
__global__ void k_split_all(const float* __restrict__ Wqkv, const float* __restrict__ Wo,
                            const float* __restrict__ W1,   const float* __restrict__ W2,
                            __half* wqh, __half* wql, __half* woh, __half* wol,
                            __half* w1h, __half* w1l, __half* w2h, __half* w2l)
{
    const int N0 = NL * 3 * DM * DM / 4;
    const int N1 = NL * DM * DM / 4;
    const int N2 = NL * DFF * DM / 4;
    const int N3 = NL * DM * DFF / 4;
    int i = blockIdx.x * blockDim.x + threadIdx.x;
    const float* s; __half *h, *l; int j;
    if (i < N0)                { s = Wqkv; h = wqh; l = wql; j = i; }
    else if (i < N0+N1)        { s = Wo;   h = woh; l = wol; j = i - N0; }
    else if (i < N0+N1+N2)     { s = W1;   h = w1h; l = w1l; j = i - N0 - N1; }
    else if (i < N0+N1+N2+N3)  { s = W2;   h = w2h; l = w2l; j = i - N0 - N1 - N2; }
    else return;
    float v[4];
    *(float4*)v = *(const float4*)(s + (size_t)j * 4);
    uint32_t hi0, lo0, hi1, lo1;
    hsplit2(v[0], v[1], hi0, lo0);
    hsplit2(v[2], v[3], hi1, lo1);
    *(uint32_t*)(h + (size_t)j * 4)     = hi0;
    *(uint32_t*)(h + (size_t)j * 4 + 2) = hi1;
    *(uint32_t*)(l + (size_t)j * 4)     = lo0;
    *(uint32_t*)(l + (size_t)j * 4 + 2) = lo1;
}

// ======================= layout transposes =======================
__global__ void k_in(const float* __restrict__ x, float* __restrict__ xb,
                     __half* __restrict__ x16) {
    int idx = blockIdx.x * blockDim.x + threadIdx.x;
    if (idx >= MTOT * DM) return;
    int kcol = idx % DM;
    int row  = idx / DM;
    int b = row / SEQ, s = row % SEQ;
    float v = x[((size_t)(s * BATCH + b)) * DM + kcol];
    xb[idx] = v;
    x16[idx] = __float2half(v);
}

__global__ void k_out(const float* __restrict__ xb, float* __restrict__ out) {
    int idx = blockIdx.x * blockDim.x + threadIdx.x;
    if (idx >= MTOT * DM) return;
    int kcol = idx % DM;
    int r    = idx / DM;
    int b = r % BATCH, s = r / BATCH;
    out[idx] = xb[((size_t)(b * SEQ + s)) * DM + kcol];
}

// ======================= fp16 HMMA GEMM: 256x128 tile, 2-term split =======================
// C[M,N] = A[M,K] * (Bh+Bl)[N,K]^T + bias. A single fp16, B fp16 hi/lo.
// OMODE: 0 = fp32 out, 1 = fp16 hi/lo out (for attention), 2 = fp16 out.
#define PAD    72
#define A16_B  (256 * PAD * 2)        // 36864
#define BH_B   (128 * PAD * 2)        // 18432
#define STG_B  (A16_B + 2 * BH_B)     // 73728
#define TG_SMEM (2 * STG_B)           // 147456

template<int RELU, int OMODE>
__global__ void __launch_bounds__(256, 1)
k_tgemm(const __half* __restrict__ A,
        const __half* __restrict__ Bh, const __half* __restrict__ Bl,
        const float* __restrict__ bias,
        float* __restrict__ Cf, __half* __restrict__ Ch, __half* __restrict__ Cl,
        __half* __restrict__ C16,
        int M, int N, int K)
{
    extern __shared__ char dsm[];
    const uint32_t sbase = smem_to_u32(dsm);
    const int tid  = threadIdx.x;
    const int lane = tid & 31;
    const int wid  = tid >> 5;
    const int wm   = wid >> 1;          // 0..3 (64-row slab)
    const int wn   = wid & 1;           // 0..1 (64-col slab)
    const int m0 = blockIdx.y * 256;
    const int n0 = blockIdx.x * 128;
    const int nch = K >> 6;

    float acc[4][8][4];
#pragma unroll
    for (int mt = 0; mt < 4; mt++)
#pragma unroll
        for (int nt = 0; nt < 8; nt++)
#pragma unroll
            for (int i = 0; i < 4; i++) acc[mt][nt][i] = 0.f;

    const uint32_t aoff = ((wm * 64 + (lane & 15)) * PAD + (lane >> 4) * 8) * 2;
    const uint32_t boff = ((wn * 64 + (lane & 7)) * PAD + ((lane >> 3) & 1) * 8) * 2;

    auto load_chunk = [&](int cc, int s) {
        uint32_t stg = sbase + s * STG_B;
#pragma unroll
        for (int i = 0; i < 16; i++) {
            int idx = tid + i * 256;
            if (idx < 2048) {
                int r = idx >> 3, c = idx & 7;
                cpa16(stg + r * (PAD * 2) + c * 16,
                      A + (size_t)(m0 + r) * K + cc * 64 + c * 8);
            } else {
                int j = idx - 2048;
                int t = j >> 10, loc = j & 1023;
                int r = loc >> 3, c = loc & 7;
                cpa16(stg + A16_B + t * BH_B + r * (PAD * 2) + c * 16,
                      (t ? Bl : Bh) + (size_t)(n0 + r) * K + cc * 64 + c * 8);
            }
        }
    };

    load_chunk(0, 0);
    asm volatile("cp.async.commit_group;" ::: "memory");

    for (int cch = 0; cch < nch; cch++) {
        __syncthreads();
        if (cch + 1 < nch) load_chunk(cch + 1, (cch + 1) & 1);
        asm volatile("cp.async.commit_group;" ::: "memory");
        asm volatile("cp.async.wait_group 1;" ::: "memory");
        __syncthreads();

        const uint32_t stg = sbase + (cch & 1) * STG_B;
        const uint32_t A_s = stg;
        const uint32_t Bh_s = stg + A16_B, Bl_s = stg + A16_B + BH_B;

#pragma unroll
        for (int ks = 0; ks < 4; ks++) {
            uint32_t bh[8][2], bl[8][2];
#pragma unroll
            for (int nt = 0; nt < 8; nt++) {
                uint32_t off = boff + (nt * 8 * PAD + ks * 16) * 2;
                ldsm_x2(bh[nt], Bh_s + off);
                ldsm_x2(bl[nt], Bl_s + off);
            }
#pragma unroll
            for (int mt = 0; mt < 4; mt++) {
                uint32_t ah[4];
                ldsm_x4(ah, A_s + aoff + (mt * 16 * PAD + ks * 16) * 2);
#pragma unroll
                for (int nt = 0; nt < 8; nt++) {
                    mma16816h(acc[mt][nt], ah, bh[nt]);
                    mma16816h(acc[mt][nt], ah, bl[nt]);
                }
            }
        }
    }

    const int r0 = m0 + wm * 64 + (lane >> 2);
    const int c0 = n0 + wn * 64 + 2 * (lane & 3);
#pragma unroll
    for (int mt = 0; mt < 4; mt++) {
#pragma unroll
        for (int nt = 0; nt < 8; nt++) {
            int col = c0 + nt * 8;
            float b0 = bias[col], b1 = bias[col + 1];
#pragma unroll
            for (int half = 0; half < 2; half++) {
                int row = r0 + mt * 16 + half * 8;
                float v0 = acc[mt][nt][2 * half + 0] + b0;
                float v1 = acc[mt][nt][2 * half + 1] + b1;
                if (RELU) { v0 = fmaxf(v0, 0.f); v1 = fmaxf(v1, 0.f); }
                size_t off = (size_t)row * N + col;
                if (OMODE == 0) {
                    float2 w = {v0, v1};
                    *(float2*)(Cf + off) = w;
                } else if (OMODE == 1) {
                    uint32_t hi, lo;
                    hsplit2(v0, v1, hi, lo);
                    *(uint32_t*)(Ch + off) = hi;
                    *(uint32_t*)(Cl + off) = lo;
                } else {
                    *(uint32_t*)(C16 + off) = packh2(v0, v1);
                }
            }
        }
    }
}

// ======================= fp16 HMMA banded flash attention (2-term, no running max) =======================
// S = Q.Kh + Q.Kl (Q = hi only); O = P.Vh + P.Vl (P single fp16).
#define AP     72
#define AROWB  (AP * 2)
#define QTILEB (128 * AROWB)
#define ATILEB (64 * AROWB)
#define ASTGB  (4 * ATILEB)
#define ATT_SMEM (QTILEB + 2 * ASTGB)

__global__ void __launch_bounds__(256, 1)
k_attn(const __half* __restrict__ qh, const __half* __restrict__ ql,
       __half* __restrict__ a16)
{
    extern __shared__ char asm_[];
    const uint32_t sbase = smem_to_u32(asm_);
    const uint32_t Qh_s = sbase;
    const uint32_t stg0 = sbase + QTILEB;

    const int tid = threadIdx.x;
    const int lane = tid & 31;
    const int w = tid >> 5;
    const int Qb = (gridDim.x - 1) - blockIdx.x;     // heavy tiles first
    const int h = blockIdx.y, b = blockIdx.z;
    const int nch = min(16, 2 * Qb + 3);
    const size_t rstr = 3 * DM;
    const size_t rowoff0 = (size_t)(b * SEQ) * rstr + h * HD;

    // Q tile: hi only
#pragma unroll
    for (int i = 0; i < 4; i++) {
        int lin = i * 256 + tid;
        int r = lin >> 3, p = lin & 7;
        cpa16(Qh_s + r * AROWB + p * 16,
              qh + rowoff0 + (size_t)(Qb * 128 + r) * rstr + p * 8);
    }
    // chunk 0: Kh, Kl, Vh, Vl
#pragma unroll
    for (int i = 0; i < 8; i++) {
        int lin = i * 256 + tid;
        int t = lin >> 9, loc = lin & 511;
        int r = loc >> 3, p = loc & 7;
        const __half* src = ((t & 1) ? ql : qh) + rowoff0
            + (size_t)(0 + r) * rstr + ((t < 2) ? DM : 2 * DM) + p * 8;
        cpa16(stg0 + t * ATILEB + r * AROWB + p * 16, src);
    }
    asm volatile("cp.async.commit_group;" ::: "memory");
    asm volatile("cp.async.wait_group 0;" ::: "memory");
    __syncthreads();

    uint32_t qf[4][4];
    {
        uint32_t qaddr = ((w * 16 + (lane & 15)) * AROWB) + (lane >> 4) * 16;
#pragma unroll
        for (int ks = 0; ks < 4; ks++)
            ldsm_x4(qf[ks], Qh_s + qaddr + ks * 32);
    }

    float oacc[8][4];
#pragma unroll
    for (int nt = 0; nt < 8; nt++)
#pragma unroll
        for (int i = 0; i < 4; i++) oacc[nt][i] = 0.f;
    float l0 = 0.f, l1 = 0.f;

    const int q0 = Qb * 128 + w * 16 + (lane >> 2);
    const int lim0 = q0 + WIN, lim1 = q0 + 8 + WIN;
    const int limw = Qb * 128 + w * 16 + 15 + WIN;
    const uint32_t kfoff = ((lane & 7) * AROWB) + ((lane >> 3) & 1) * 16;
    const uint32_t vfoff = ((lane & 15) * AROWB);

    for (int c = 0; c < nch; c++) {
        if (c > 0) {
            asm volatile("cp.async.wait_group 0;" ::: "memory");
            __syncthreads();
        }
        if (c + 1 < nch) {
            uint32_t stg = stg0 + ((c + 1) & 1) * ASTGB;
#pragma unroll
            for (int i = 0; i < 8; i++) {
                int lin = i * 256 + tid;
                int t = lin >> 9, loc = lin & 511;
                int r = loc >> 3, p = loc & 7;
                const __half* src = ((t & 1) ? ql : qh) + rowoff0
                    + (size_t)((c + 1) * 64 + r) * rstr + ((t < 2) ? DM : 2 * DM) + p * 8;
                cpa16(stg + t * ATILEB + r * AROWB + p * 16, src);
            }
        }
        asm volatile("cp.async.commit_group;" ::: "memory");

        if (c * 64 > limw) continue;

        const uint32_t stg = stg0 + (c & 1) * ASTGB;
        const uint32_t Kh_s = stg, Kl_s = stg + ATILEB;
        const uint32_t Vh_s = stg + 2 * ATILEB, Vl_s = stg + 3 * ATILEB;

        float sacc[8][4];
#pragma unroll
        for (int nt = 0; nt < 8; nt++)
#pragma unroll
            for (int i = 0; i < 4; i++) sacc[nt][i] = 0.f;
#pragma unroll
        for (int ks = 0; ks < 4; ks++) {
#pragma unroll
            for (int nt = 0; nt < 8; nt++) {
                uint32_t kh[2], kl[2];
                uint32_t off = nt * 8 * AROWB + kfoff + ks * 32;
                ldsm_x2(kh, Kh_s + off);
                ldsm_x2(kl, Kl_s + off);
                mma16816h(sacc[nt], qf[ks], kh);
                mma16816h(sacc[nt], qf[ks], kl);
            }
        }

        const float scale = 0.125f;
        const bool domask = (c >= 2 * Qb + 1);
        const int jb = c * 64 + 2 * (lane & 3);
#pragma unroll
        for (int nt = 0; nt < 8; nt++) {
            int j0 = jb + nt * 8, j1 = j0 + 1;
            float s0 = sacc[nt][0] * scale, s1 = sacc[nt][1] * scale;
            float s2 = sacc[nt][2] * scale, s3 = sacc[nt][3] * scale;
            if (domask) {
                if (j0 > lim0) s0 = -1e30f;
                if (j1 > lim0) s1 = -1e30f;
                if (j0 > lim1) s2 = -1e30f;
                if (j1 > lim1) s3 = -1e30f;
            }
            float p0 = __expf(s0), p1 = __expf(s1);
            float p2 = __expf(s2), p3 = __expf(s3);
            sacc[nt][0] = p0; sacc[nt][1] = p1; sacc[nt][2] = p2; sacc[nt][3] = p3;
            l0 += p0 + p1; l1 += p2 + p3;
        }

#pragma unroll
        for (int kk = 0; kk < 4; kk++) {
            uint32_t pa[4];
            pa[0] = packh2(sacc[2*kk][0],   sacc[2*kk][1]);
            pa[1] = packh2(sacc[2*kk][2],   sacc[2*kk][3]);
            pa[2] = packh2(sacc[2*kk+1][0], sacc[2*kk+1][1]);
            pa[3] = packh2(sacc[2*kk+1][2], sacc[2*kk+1][3]);
#pragma unroll
            for (int nt = 0; nt < 8; nt++) {
                uint32_t vh[2], vl[2];
                uint32_t off = kk * 16 * AROWB + vfoff + nt * 16;
                ldsm_x2t(vh, Vh_s + off);
                ldsm_x2t(vl, Vl_s + off);
                mma16816h(oacc[nt], pa, vh);
                mma16816h(oacc[nt], pa, vl);
            }
        }
    }

    l0 += __shfl_xor_sync(~0u, l0, 1); l0 += __shfl_xor_sync(~0u, l0, 2);
    l1 += __shfl_xor_sync(~0u, l1, 1); l1 += __shfl_xor_sync(~0u, l1, 2);
    float inv0 = 1.0f / l0, inv1 = 1.0f / l1;
    size_t orow0 = (size_t)(b * SEQ + q0) * DM + h * HD;
    size_t orow1 = orow0 + (size_t)8 * DM;
    int cbase = 2 * (lane & 3);
#pragma unroll
    for (int nt = 0; nt < 8; nt++) {
        int col = cbase + nt * 8;
        *(uint32_t*)(a16 + orow0 + col) = packh2(oacc[nt][0] * inv0, oacc[nt][1] * inv0);
        *(uint32_t*)(a16 + orow1 + col) = packh2(oacc[nt][2] * inv1, oacc[nt][3] * inv1);
    }
}

// ======================= LayerNorm(resid + delta) -> fp32 + fp16 =======================
__global__ void __launch_bounds__(256)
k_ln(const float* __restrict__ resid, const float* __restrict__ delta,
     const float* __restrict__ gamma, const float* __restrict__ beta,
     float* __restrict__ out, __half* __restrict__ o16)
{
    __shared__ float red[8];
    const int row = blockIdx.x;
    const int t = threadIdx.x;
    const float* rp = resid + (size_t)row * DM;
    const float* dp = delta + (size_t)row * DM;

    float4 rv = *(const float4*)(rp + t * 4);
    float4 dv = *(const float4*)(dp + t * 4);
    float v[4] = {rv.x + dv.x, rv.y + dv.y, rv.z + dv.z, rv.w + dv.w};

    float s = v[0] + v[1] + v[2] + v[3];
#pragma unroll
    for (int off = 16; off; off >>= 1) s += __shfl_xor_sync(~0u, s, off);
    if ((t & 31) == 0) red[t >> 5] = s;
    __syncthreads();
    if (t < 8) {
        float x = red[t];
#pragma unroll
        for (int off = 4; off; off >>= 1) x += __shfl_xor_sync(0xffu, x, off);
        if (t == 0) red[0] = x;
    }
    __syncthreads();
    float mu = red[0] * (1.0f / DM);
    __syncthreads();

    float vs = 0.f;
#pragma unroll
    for (int i = 0; i < 4; i++) { float d = v[i] - mu; vs += d * d; }
#pragma unroll
    for (int off = 16; off; off >>= 1) vs += __shfl_xor_sync(~0u, vs, off);
    if ((t & 31) == 0) red[t >> 5] = vs;
    __syncthreads();
    if (t < 8) {
        float x = red[t];
#pragma unroll
        for (int off = 4; off; off >>= 1) x += __shfl_xor_sync(0xffu, x, off);
        if (t == 0) red[0] = x;
    }
    __syncthreads();
    float rstd = rsqrtf(red[0] * (1.0f / DM) + 1e-5f);

    float4 g4 = *(const float4*)(gamma + t * 4);
    float4 b4 = *(const float4*)(beta  + t * 4);
    float w[4];
    w[0] = (v[0] - mu) * rstd * g4.x + b4.x;
    w[1] = (v[1] - mu) * rstd * g4.y + b4.y;
    w[2] = (v[2] - mu) * rstd * g4.z + b4.z;
    w[3] = (v[3] - mu) * rstd * g4.w + b4.w;
    float4 wf = {w[0], w[1], w[2], w[3]};
    size_t o4 = (size_t)row * DM + t * 4;
    *(float4*)(out + o4) = wf;
    *(uint32_t*)(o16 + o4)     = packh2(w[0], w[1]);
    *(uint32_t*)(o16 + o4 + 2) = packh2(w[2], w[3]);
}

// ======================= host driver =======================
extern "C" void kernel_launch(void* const* d_in, const int* in_sizes, int n_in,
                              void* d_out, int out_size)
{
    const float* x    = (const float*)d_in[0];
    const float* Wqkv = (const float*)d_in[1];
    const float* bqkv = (const float*)d_in[2];
    const float* Wo   = (const float*)d_in[3];
    const float* bo   = (const float*)d_in[4];
    const float* W1   = (const float*)d_in[5];
    const float* b1   = (const float*)d_in[6];
    const float* W2   = (const float*)d_in[7];
    const float* b2   = (const float*)d_in[8];
    const float* g1   = (const float*)d_in[9];
    const float* be1  = (const float*)d_in[10];
    const float* g2   = (const float*)d_in[11];
    const float* be2  = (const float*)d_in[12];
    float* out = (float*)d_out;

    float *p_xb, *p_delta;
    __half *p_x16, *p_a16, *p_f16, *p_qkvh, *p_qkvl;
    __half *p_wqh, *p_wql, *p_woh, *p_wol, *p_w1h, *p_w1l, *p_w2h, *p_w2l;
    cudaGetSymbolAddress((void**)&p_xb,  g_xb);
    cudaGetSymbolAddress((void**)&p_delta, g_delta);
    cudaGetSymbolAddress((void**)&p_x16, g_x16);
    cudaGetSymbolAddress((void**)&p_a16, g_a16);
    cudaGetSymbolAddress((void**)&p_f16, g_f16);
    cudaGetSymbolAddress((void**)&p_qkvh, g_qkvh);
    cudaGetSymbolAddress((void**)&p_qkvl, g_qkvl);
    cudaGetSymbolAddress((void**)&p_wqh, g_wqh);
    cudaGetSymbolAddress((void**)&p_wql, g_wql);
    cudaGetSymbolAddress((void**)&p_woh, g_woh);
    cudaGetSymbolAddress((void**)&p_wol, g_wol);
    cudaGetSymbolAddress((void**)&p_w1h, g_w1h);
    cudaGetSymbolAddress((void**)&p_w1l, g_w1l);
    cudaGetSymbolAddress((void**)&p_w2h, g_w2h);
    cudaGetSymbolAddress((void**)&p_w2l, g_w2l);

    cudaFuncSetAttribute(k_tgemm<0,0>, cudaFuncAttributeMaxDynamicSharedMemorySize, TG_SMEM);
    cudaFuncSetAttribute(k_tgemm<0,1>, cudaFuncAttributeMaxDynamicSharedMemorySize, TG_SMEM);
    cudaFuncSetAttribute(k_tgemm<1,2>, cudaFuncAttributeMaxDynamicSharedMemorySize, TG_SMEM);
    cudaFuncSetAttribute(k_attn, cudaFuncAttributeMaxDynamicSharedMemorySize, ATT_SMEM);

    {
        int ntot = (NL * 3 * DM * DM + NL * DM * DM + NL * DFF * DM + NL * DM * DFF) / 4;
        k_split_all<<<(ntot + 255) / 256, 256>>>(Wqkv, Wo, W1, W2,
            p_wqh, p_wql, p_woh, p_wol, p_w1h, p_w1l, p_w2h, p_w2l);
    }

    const int nElem = MTOT * DM;
    k_in<<<(nElem + 255) / 256, 256>>>(x, p_xb, p_x16);

    for (int l = 0; l < NL; l++) {
        // QKV projection -> fp16 hi/lo for attention
        k_tgemm<0,1><<<dim3(3 * DM / 128, MTOT / 256), 256, TG_SMEM>>>(
            p_x16,
            p_wqh + (size_t)l * 3 * DM * DM, p_wql + (size_t)l * 3 * DM * DM,
            bqkv + (size_t)l * 3 * DM,
            nullptr, p_qkvh, p_qkvl, nullptr, MTOT, 3 * DM, DM);

        // attention (fp16 2-term) -> single fp16
        k_attn<<<dim3(SEQ / 128, NH, BATCH), 256, ATT_SMEM>>>(p_qkvh, p_qkvl, p_a16);

        // output projection -> fp32 delta
        k_tgemm<0,0><<<dim3(DM / 128, MTOT / 256), 256, TG_SMEM>>>(
            p_a16,
            p_woh + (size_t)l * DM * DM, p_wol + (size_t)l * DM * DM,
            bo + (size_t)l * DM,
            p_delta, nullptr, nullptr, nullptr, MTOT, DM, DM);

        k_ln<<<MTOT, 256>>>(p_xb, p_delta, g1 + (size_t)l * DM, be1 + (size_t)l * DM,
                            p_xb, p_x16);

        // FF1 + ReLU -> single fp16
        k_tgemm<1,2><<<dim3(DFF / 128, MTOT / 256), 256, TG_SMEM>>>(
            p_x16,
            p_w1h + (size_t)l * DFF * DM, p_w1l + (size_t)l * DFF * DM,
            b1 + (size_t)l * DFF,
            nullptr, nullptr, nullptr, p_f16, MTOT, DFF, DM);

        // FF2 -> fp32 delta
        k_tgemm<0,0><<<dim3(DM / 128, MTOT / 256), 256, TG_SMEM>>>(
            p_f16,
            p_w2h + (size_t)l * DM * DFF, p_w2l + (size_t)l * DM * DFF,
            b2 + (size_t)l * DM,
            p_delta, nullptr, nullptr, nullptr, MTOT, DM, DFF);

        k_ln<<<MTOT, 256>>>(p_xb, p_delta, g2 + (size_t)l * DM, be2 + (size_t)l * DM,
                            p_xb, p_x16);
    }

    k_out<<<(nElem + 255) / 256, 256>>>(p_xb, out);
}